// round 5
// baseline (speedup 1.0000x reference)
#include <cuda_runtime.h>
#include <cuda_bf16.h>
#include <math.h>

#define N_NODES 100000
#define N_EDGES 800000
#define F_IN 256
#define HID 128
#define N_CLS 32

// ---------------- scratch (device globals; no allocation allowed) ----------------
__device__ int   g_flag;                    // 1 if edge_index is int64, 0 if int32
__device__ int   g_src[N_EDGES];
__device__ int   g_dst[N_EDGES];
__device__ int   g_deg[N_NODES];            // in-degree of real edges
__device__ int   g_cursor[N_NODES];
__device__ int   g_rowstart[N_NODES];
__device__ int   g_csr_src[N_EDGES];        // src node per CSR slot (bucketed by dst)
__device__ float g_dinv[N_NODES];
__device__ float g_xw[N_NODES * HID];       // X @ W1
__device__ float g_h[N_NODES * HID];        // layer-1 output (post relu)
__device__ float g_hw2[N_NODES * N_CLS];    // H @ W2

// ---------------- edge dtype detection ----------------
__global__ __launch_bounds__(32)
void k_detect(const int* e_as_i32) {
    if (threadIdx.x == 0 && blockIdx.x == 0) {
        // int64 little-endian nonneg small values -> odd 32-bit words are all 0
        bool is64 = true;
        for (int i = 0; i < 64; i++) {
            if (e_as_i32[2 * i + 1] != 0) { is64 = false; break; }
        }
        g_flag = is64 ? 1 : 0;
    }
}

__global__ __launch_bounds__(256)
void k_init() {
    int i = blockIdx.x * blockDim.x + threadIdx.x;
    if (i < N_NODES) { g_deg[i] = 0; g_cursor[i] = 0; }
}

__global__ __launch_bounds__(256)
void k_convert(const void* eidx) {
    int e = blockIdx.x * blockDim.x + threadIdx.x;
    if (e >= N_EDGES) return;
    int s, d;
    if (g_flag) {
        const long long* p = (const long long*)eidx;
        s = (int)p[e];
        d = (int)p[N_EDGES + e];
    } else {
        const int* p = (const int*)eidx;
        s = p[e];
        d = p[N_EDGES + e];
    }
    g_src[e] = s;
    g_dst[e] = d;
    atomicAdd(&g_deg[d], 1);
}

__global__ __launch_bounds__(256)
void k_dinv() {
    int i = blockIdx.x * blockDim.x + threadIdx.x;
    if (i < N_NODES) g_dinv[i] = rsqrtf((float)(g_deg[i] + 1));  // +1 self loop
}

// single-block exclusive scan of g_deg -> g_rowstart (512 threads)
__global__ __launch_bounds__(512)
void k_scan() {
    __shared__ int sums[512];
    const int t = threadIdx.x;
    const int PER = (N_NODES + 511) / 512;  // 196
    int base = t * PER;
    int s = 0;
    for (int i = 0; i < PER; i++) {
        int idx = base + i;
        if (idx < N_NODES) s += g_deg[idx];
    }
    sums[t] = s;
    __syncthreads();
    // Hillis-Steele inclusive scan
    for (int off = 1; off < 512; off <<= 1) {
        int v = (t >= off) ? sums[t - off] : 0;
        __syncthreads();
        sums[t] += v;
        __syncthreads();
    }
    int run = (t == 0) ? 0 : sums[t - 1];
    for (int i = 0; i < PER; i++) {
        int idx = base + i;
        if (idx < N_NODES) {
            g_rowstart[idx] = run;
            run += g_deg[idx];
        }
    }
}

__global__ __launch_bounds__(256)
void k_fill() {
    int e = blockIdx.x * blockDim.x + threadIdx.x;
    if (e >= N_EDGES) return;
    int d = g_dst[e];
    int pos = atomicAdd(&g_cursor[d], 1);
    g_csr_src[g_rowstart[d] + pos] = g_src[e];
}

// ---------------- generic register-blocked fp32 SGEMM ----------------
// C[M,N] = A[M,K] @ B[K,N], all row-major. K % BK == 0, N % BN == 0 assumed.
template <int BM, int BN, int BK, int TM, int TN>
__global__ __launch_bounds__((BM / TM) * (BN / TN))
void k_sgemm(const float* __restrict__ A, const float* __restrict__ B,
             float* __restrict__ C, int M, int N, int K) {
    constexpr int THREADS = (BM / TM) * (BN / TN);
    __shared__ float As[BK][BM];
    __shared__ float Bs[BK][BN];
    const int m0 = blockIdx.x * BM;
    const int tid = threadIdx.x;
    constexpr int TCOLS = BN / TN;
    const int tc = tid % TCOLS;
    const int tr = tid / TCOLS;

    float acc[TM][TN];
#pragma unroll
    for (int i = 0; i < TM; i++)
#pragma unroll
        for (int j = 0; j < TN; j++) acc[i][j] = 0.0f;

    for (int k0 = 0; k0 < K; k0 += BK) {
        // load A tile (BM x BK), transposed into As
#pragma unroll
        for (int i = tid * 4; i < BM * BK; i += THREADS * 4) {
            int r = i / BK, c = i % BK;
            float4 v = make_float4(0.f, 0.f, 0.f, 0.f);
            int gr = m0 + r;
            if (gr < M) v = *reinterpret_cast<const float4*>(&A[(size_t)gr * K + k0 + c]);
            As[c + 0][r] = v.x;
            As[c + 1][r] = v.y;
            As[c + 2][r] = v.z;
            As[c + 3][r] = v.w;
        }
        // load B tile (BK x BN)
#pragma unroll
        for (int i = tid * 4; i < BK * BN; i += THREADS * 4) {
            int r = i / BN, c = i % BN;
            *reinterpret_cast<float4*>(&Bs[r][c]) =
                *reinterpret_cast<const float4*>(&B[(size_t)(k0 + r) * N + c]);
        }
        __syncthreads();
#pragma unroll
        for (int k = 0; k < BK; k++) {
            float a[TM], b[TN];
#pragma unroll
            for (int i = 0; i < TM; i++) a[i] = As[k][tr * TM + i];
#pragma unroll
            for (int j = 0; j < TN; j++) b[j] = Bs[k][tc * TN + j];
#pragma unroll
            for (int i = 0; i < TM; i++)
#pragma unroll
                for (int j = 0; j < TN; j++) acc[i][j] += a[i] * b[j];
        }
        __syncthreads();
    }
#pragma unroll
    for (int i = 0; i < TM; i++) {
        int gr = m0 + tr * TM + i;
        if (gr < M) {
#pragma unroll
            for (int j = 0; j < TN; j += 4) {
                *reinterpret_cast<float4*>(&C[(size_t)gr * N + tc * TN + j]) =
                    make_float4(acc[i][j], acc[i][j + 1], acc[i][j + 2], acc[i][j + 3]);
            }
        }
    }
}

// ---------------- layer-1 aggregation: warp per node, 128 features ----------------
__global__ __launch_bounds__(256)
void k_agg1(const float* __restrict__ b1) {
    int node = (blockIdx.x * blockDim.x + threadIdx.x) >> 5;
    int lane = threadIdx.x & 31;
    if (node >= N_NODES) return;
    float di = g_dinv[node];
    const float4* xw4 = reinterpret_cast<const float4*>(g_xw);
    float4 self = xw4[(size_t)node * 32 + lane];
    float w0 = di * di;
    float4 acc = make_float4(self.x * w0, self.y * w0, self.z * w0, self.w * w0);
    int start = g_rowstart[node];
    int cnt = g_deg[node];
    for (int e = 0; e < cnt; e++) {
        int s = g_csr_src[start + e];
        float w = di * g_dinv[s];
        float4 v = xw4[(size_t)s * 32 + lane];
        acc.x += w * v.x;
        acc.y += w * v.y;
        acc.z += w * v.z;
        acc.w += w * v.w;
    }
    float4 bb = reinterpret_cast<const float4*>(b1)[lane];
    acc.x = fmaxf(acc.x + bb.x, 0.0f);
    acc.y = fmaxf(acc.y + bb.y, 0.0f);
    acc.z = fmaxf(acc.z + bb.z, 0.0f);
    acc.w = fmaxf(acc.w + bb.w, 0.0f);
    reinterpret_cast<float4*>(g_h)[(size_t)node * 32 + lane] = acc;
}

// ---------------- layer-2 aggregation + bias + log_softmax ----------------
__global__ __launch_bounds__(256)
void k_agg2(const float* __restrict__ b2, float* __restrict__ out) {
    int node = (blockIdx.x * blockDim.x + threadIdx.x) >> 5;
    int lane = threadIdx.x & 31;
    if (node >= N_NODES) return;
    float di = g_dinv[node];
    float acc = di * di * g_hw2[(size_t)node * N_CLS + lane];
    int start = g_rowstart[node];
    int cnt = g_deg[node];
    for (int e = 0; e < cnt; e++) {
        int s = g_csr_src[start + e];
        float w = di * g_dinv[s];
        acc += w * g_hw2[(size_t)s * N_CLS + lane];
    }
    acc += b2[lane];
    // log_softmax over the 32 lanes
    float m = acc;
#pragma unroll
    for (int off = 16; off > 0; off >>= 1)
        m = fmaxf(m, __shfl_xor_sync(0xFFFFFFFFu, m, off));
    float ex = expf(acc - m);
    float sum = ex;
#pragma unroll
    for (int off = 16; off > 0; off >>= 1)
        sum += __shfl_xor_sync(0xFFFFFFFFu, sum, off);
    out[(size_t)node * N_CLS + lane] = acc - m - logf(sum);
}

// ---------------- launch ----------------
extern "C" void kernel_launch(void* const* d_in, const int* in_sizes, int n_in,
                              void* d_out, int out_size) {
    const float* features = nullptr;
    const void*  eidx = nullptr;
    const float* W1 = nullptr;
    const float* b1 = nullptr;
    const float* W2 = nullptr;
    const float* b2 = nullptr;
    for (int i = 0; i < n_in; i++) {
        switch (in_sizes[i]) {
            case N_NODES * F_IN: features = (const float*)d_in[i]; break;
            case 2 * N_EDGES:    eidx = d_in[i]; break;
            case F_IN * HID:     W1 = (const float*)d_in[i]; break;
            case HID:            b1 = (const float*)d_in[i]; break;
            case HID * N_CLS:    W2 = (const float*)d_in[i]; break;
            case N_CLS:          b2 = (const float*)d_in[i]; break;
            default: break;
        }
    }

    void *p_xw = nullptr, *p_h = nullptr, *p_hw2 = nullptr;
    cudaGetSymbolAddress(&p_xw, g_xw);
    cudaGetSymbolAddress(&p_h, g_h);
    cudaGetSymbolAddress(&p_hw2, g_hw2);

    // preprocessing
    k_detect<<<1, 32>>>((const int*)eidx);
    k_init<<<(N_NODES + 255) / 256, 256>>>();
    k_convert<<<(N_EDGES + 255) / 256, 256>>>(eidx);
    k_dinv<<<(N_NODES + 255) / 256, 256>>>();
    k_scan<<<1, 512>>>();
    k_fill<<<(N_EDGES + 255) / 256, 256>>>();

    // layer 1: XW1 then aggregate+bias+relu
    {
        constexpr int BM = 64;
        int grid = (N_NODES + BM - 1) / BM;
        k_sgemm<BM, 128, 16, 4, 8><<<grid, 256>>>(features, W1, (float*)p_xw,
                                                  N_NODES, HID, F_IN);
    }
    k_agg1<<<(N_NODES * 32 + 255) / 256, 256>>>(b1);

    // layer 2: HW2 then aggregate+bias+log_softmax
    {
        constexpr int BM = 128;
        int grid = (N_NODES + BM - 1) / BM;
        k_sgemm<BM, 32, 16, 8, 4><<<grid, 128>>>((const float*)p_h, W2, (float*)p_hw2,
                                                 N_NODES, N_CLS, HID);
    }
    k_agg2<<<(N_NODES * 32 + 255) / 256, 256>>>(b2, (float*)d_out);
}

// round 6
// speedup vs baseline: 1.6110x; 1.6110x over previous
#include <cuda_runtime.h>
#include <cuda_bf16.h>
#include <math.h>
#include <stdint.h>

#define N_NODES 100000
#define N_EDGES 800000
#define F_IN 256
#define HID 128
#define N_CLS 32

// ---------------- scratch (device globals; no allocation allowed) ----------------
__device__ int   g_flag;                    // 1 if edge_index is int64, 0 if int32
__device__ int   g_src[N_EDGES];
__device__ int   g_dst[N_EDGES];
__device__ int   g_deg[N_NODES];            // in-degree of real edges
__device__ int   g_cursor[N_NODES];
__device__ int   g_rowstart[N_NODES];
__device__ int   g_csr_src[N_EDGES];        // src node per CSR slot (bucketed by dst)
__device__ float g_dinv[N_NODES];
__device__ float g_xw[N_NODES * HID];       // X @ W1
__device__ float g_h[N_NODES * HID];        // layer-1 output (post relu)
__device__ float g_hw2[N_NODES * N_CLS];    // H @ W2

// ---------------- edge dtype detection ----------------
__global__ __launch_bounds__(32)
void k_detect(const int* e_as_i32) {
    if (threadIdx.x == 0 && blockIdx.x == 0) {
        // int64 little-endian nonneg small values -> odd 32-bit words are all 0
        bool is64 = true;
        for (int i = 0; i < 64; i++) {
            if (e_as_i32[2 * i + 1] != 0) { is64 = false; break; }
        }
        g_flag = is64 ? 1 : 0;
    }
}

__global__ __launch_bounds__(256)
void k_init() {
    int i = blockIdx.x * blockDim.x + threadIdx.x;
    if (i < N_NODES) { g_deg[i] = 0; g_cursor[i] = 0; }
}

__global__ __launch_bounds__(256)
void k_convert(const void* eidx) {
    int e = blockIdx.x * blockDim.x + threadIdx.x;
    if (e >= N_EDGES) return;
    int s, d;
    if (g_flag) {
        const long long* p = (const long long*)eidx;
        s = (int)p[e];
        d = (int)p[N_EDGES + e];
    } else {
        const int* p = (const int*)eidx;
        s = p[e];
        d = p[N_EDGES + e];
    }
    g_src[e] = s;
    g_dst[e] = d;
    atomicAdd(&g_deg[d], 1);
}

__global__ __launch_bounds__(256)
void k_dinv() {
    int i = blockIdx.x * blockDim.x + threadIdx.x;
    if (i < N_NODES) g_dinv[i] = rsqrtf((float)(g_deg[i] + 1));  // +1 self loop
}

// single-block exclusive scan of g_deg -> g_rowstart (512 threads)
__global__ __launch_bounds__(512)
void k_scan() {
    __shared__ int sums[512];
    const int t = threadIdx.x;
    const int PER = (N_NODES + 511) / 512;  // 196
    int base = t * PER;
    int s = 0;
    for (int i = 0; i < PER; i++) {
        int idx = base + i;
        if (idx < N_NODES) s += g_deg[idx];
    }
    sums[t] = s;
    __syncthreads();
    // Hillis-Steele inclusive scan
    for (int off = 1; off < 512; off <<= 1) {
        int v = (t >= off) ? sums[t - off] : 0;
        __syncthreads();
        sums[t] += v;
        __syncthreads();
    }
    int run = (t == 0) ? 0 : sums[t - 1];
    for (int i = 0; i < PER; i++) {
        int idx = base + i;
        if (idx < N_NODES) {
            g_rowstart[idx] = run;
            run += g_deg[idx];
        }
    }
}

__global__ __launch_bounds__(256)
void k_fill() {
    int e = blockIdx.x * blockDim.x + threadIdx.x;
    if (e >= N_EDGES) return;
    int d = g_dst[e];
    int pos = atomicAdd(&g_cursor[d], 1);
    g_csr_src[g_rowstart[d] + pos] = g_src[e];
}

// ---------------- tf32 helpers ----------------
__device__ __forceinline__ float to_tf32(float x) {
    float r;
    asm("cvt.rna.tf32.f32 %0, %1;" : "=f"(r) : "f"(x));
    return r;
}

__device__ __forceinline__ void mma_tf32(float c[4], const uint32_t a[4], const uint32_t b[2]) {
    asm volatile(
        "mma.sync.aligned.m16n8k8.row.col.f32.tf32.tf32.f32 "
        "{%0,%1,%2,%3}, {%4,%5,%6,%7}, {%8,%9}, {%0,%1,%2,%3};"
        : "+f"(c[0]), "+f"(c[1]), "+f"(c[2]), "+f"(c[3])
        : "r"(a[0]), "r"(a[1]), "r"(a[2]), "r"(a[3]), "r"(b[0]), "r"(b[1]));
}

// ---------------- GEMM1: C[100000,128] = A[100000,256] @ B[256,128] via tf32 MMA ----------------
// Block tile 128x128, BK=32, 8 warps (4x2), warp tile 32x64 = 2x8 m16n8k8 tiles.
__global__ __launch_bounds__(256)
void k_gemm1_tf32(const float* __restrict__ A, const float* __restrict__ B,
                  float* __restrict__ C) {
    // As[m][k]: pad 36 -> fragment-load bank = (4*g + tig) % 32, conflict-free
    __shared__ float As[128][36];
    // Bs[k][n]: pad 136 -> fragment-load bank = (8*tig + g) % 32, conflict-free
    __shared__ float Bs[32][136];

    const int tid = threadIdx.x;
    const int m0 = blockIdx.x * 128;
    const int wid = tid >> 5, lane = tid & 31;
    const int g = lane >> 2, tig = lane & 3;
    const int warp_m = wid >> 1;    // 0..3
    const int warp_n = wid & 1;     // 0..1
    const int mbase = warp_m * 32;
    const int nbase = warp_n * 64;

    float c[2][8][4];
#pragma unroll
    for (int mt = 0; mt < 2; mt++)
#pragma unroll
        for (int nt = 0; nt < 8; nt++)
#pragma unroll
            for (int i = 0; i < 4; i++) c[mt][nt][i] = 0.0f;

    for (int k0 = 0; k0 < F_IN; k0 += 32) {
        // stage A tile: 128 rows x 32 k  (1024 float4 slots / 256 threads = 4)
#pragma unroll
        for (int s = 0; s < 4; s++) {
            int slot = tid + s * 256;
            int r = slot >> 3;              // 0..127
            int kk = (slot & 7) * 4;        // 0,4,...,28
            int gr = m0 + r;
            float4 v = make_float4(0.f, 0.f, 0.f, 0.f);
            if (gr < N_NODES) v = *reinterpret_cast<const float4*>(&A[(size_t)gr * F_IN + k0 + kk]);
            As[r][kk + 0] = to_tf32(v.x);
            As[r][kk + 1] = to_tf32(v.y);
            As[r][kk + 2] = to_tf32(v.z);
            As[r][kk + 3] = to_tf32(v.w);
        }
        // stage B tile: 32 k x 128 n (row-major, no transpose)
#pragma unroll
        for (int s = 0; s < 4; s++) {
            int slot = tid + s * 256;
            int kr = slot >> 5;             // 0..31
            int n = (slot & 31) * 4;        // 0,4,...,124
            float4 v = *reinterpret_cast<const float4*>(&B[(size_t)(k0 + kr) * HID + n]);
            Bs[kr][n + 0] = to_tf32(v.x);
            Bs[kr][n + 1] = to_tf32(v.y);
            Bs[kr][n + 2] = to_tf32(v.z);
            Bs[kr][n + 3] = to_tf32(v.w);
        }
        __syncthreads();

#pragma unroll
        for (int kk = 0; kk < 4; kk++) {
            const int kb = kk * 8;
            uint32_t a[2][4];
#pragma unroll
            for (int mt = 0; mt < 2; mt++) {
                int m = mbase + mt * 16 + g;
                a[mt][0] = __float_as_uint(As[m][kb + tig]);
                a[mt][1] = __float_as_uint(As[m + 8][kb + tig]);
                a[mt][2] = __float_as_uint(As[m][kb + tig + 4]);
                a[mt][3] = __float_as_uint(As[m + 8][kb + tig + 4]);
            }
            uint32_t b[8][2];
#pragma unroll
            for (int nt = 0; nt < 8; nt++) {
                int n = nbase + nt * 8 + g;
                b[nt][0] = __float_as_uint(Bs[kb + tig][n]);
                b[nt][1] = __float_as_uint(Bs[kb + tig + 4][n]);
            }
#pragma unroll
            for (int mt = 0; mt < 2; mt++)
#pragma unroll
                for (int nt = 0; nt < 8; nt++)
                    mma_tf32(c[mt][nt], a[mt], b[nt]);
        }
        __syncthreads();
    }

    // store C: c0,c1 -> (row g, cols tig*2, tig*2+1); c2,c3 -> row g+8
#pragma unroll
    for (int mt = 0; mt < 2; mt++) {
#pragma unroll
        for (int nt = 0; nt < 8; nt++) {
            int row0 = m0 + mbase + mt * 16 + g;
            int col = nbase + nt * 8 + tig * 2;
            if (row0 < N_NODES) {
                *reinterpret_cast<float2*>(&C[(size_t)row0 * HID + col]) =
                    make_float2(c[mt][nt][0], c[mt][nt][1]);
            }
            int row1 = row0 + 8;
            if (row1 < N_NODES) {
                *reinterpret_cast<float2*>(&C[(size_t)row1 * HID + col]) =
                    make_float2(c[mt][nt][2], c[mt][nt][3]);
            }
        }
    }
}

// ---------------- generic register-blocked fp32 SGEMM (layer 2) ----------------
template <int BM, int BN, int BK, int TM, int TN>
__global__ __launch_bounds__((BM / TM) * (BN / TN))
void k_sgemm(const float* __restrict__ A, const float* __restrict__ B,
             float* __restrict__ C, int M, int N, int K) {
    constexpr int THREADS = (BM / TM) * (BN / TN);
    __shared__ float As[BK][BM];
    __shared__ float Bs[BK][BN];
    const int m0 = blockIdx.x * BM;
    const int tid = threadIdx.x;
    constexpr int TCOLS = BN / TN;
    const int tc = tid % TCOLS;
    const int tr = tid / TCOLS;

    float acc[TM][TN];
#pragma unroll
    for (int i = 0; i < TM; i++)
#pragma unroll
        for (int j = 0; j < TN; j++) acc[i][j] = 0.0f;

    for (int k0 = 0; k0 < K; k0 += BK) {
#pragma unroll
        for (int i = tid * 4; i < BM * BK; i += THREADS * 4) {
            int r = i / BK, cc = i % BK;
            float4 v = make_float4(0.f, 0.f, 0.f, 0.f);
            int gr = m0 + r;
            if (gr < M) v = *reinterpret_cast<const float4*>(&A[(size_t)gr * K + k0 + cc]);
            As[cc + 0][r] = v.x;
            As[cc + 1][r] = v.y;
            As[cc + 2][r] = v.z;
            As[cc + 3][r] = v.w;
        }
#pragma unroll
        for (int i = tid * 4; i < BK * BN; i += THREADS * 4) {
            int r = i / BN, cc = i % BN;
            *reinterpret_cast<float4*>(&Bs[r][cc]) =
                *reinterpret_cast<const float4*>(&B[(size_t)(k0 + r) * N + cc]);
        }
        __syncthreads();
#pragma unroll
        for (int k = 0; k < BK; k++) {
            float a[TM], b[TN];
#pragma unroll
            for (int i = 0; i < TM; i++) a[i] = As[k][tr * TM + i];
#pragma unroll
            for (int j = 0; j < TN; j++) b[j] = Bs[k][tc * TN + j];
#pragma unroll
            for (int i = 0; i < TM; i++)
#pragma unroll
                for (int j = 0; j < TN; j++) acc[i][j] += a[i] * b[j];
        }
        __syncthreads();
    }
#pragma unroll
    for (int i = 0; i < TM; i++) {
        int gr = m0 + tr * TM + i;
        if (gr < M) {
#pragma unroll
            for (int j = 0; j < TN; j += 4) {
                *reinterpret_cast<float4*>(&C[(size_t)gr * N + tc * TN + j]) =
                    make_float4(acc[i][j], acc[i][j + 1], acc[i][j + 2], acc[i][j + 3]);
            }
        }
    }
}

// ---------------- layer-1 aggregation: warp per node, 128 features ----------------
__global__ __launch_bounds__(256)
void k_agg1(const float* __restrict__ b1) {
    int node = (blockIdx.x * blockDim.x + threadIdx.x) >> 5;
    int lane = threadIdx.x & 31;
    if (node >= N_NODES) return;
    float di = g_dinv[node];
    const float4* xw4 = reinterpret_cast<const float4*>(g_xw);
    float4 self = xw4[(size_t)node * 32 + lane];
    float w0 = di * di;
    float4 acc = make_float4(self.x * w0, self.y * w0, self.z * w0, self.w * w0);
    int start = g_rowstart[node];
    int cnt = g_deg[node];
#pragma unroll 4
    for (int e = 0; e < cnt; e++) {
        int s = g_csr_src[start + e];
        float w = di * g_dinv[s];
        float4 v = xw4[(size_t)s * 32 + lane];
        acc.x += w * v.x;
        acc.y += w * v.y;
        acc.z += w * v.z;
        acc.w += w * v.w;
    }
    float4 bb = reinterpret_cast<const float4*>(b1)[lane];
    acc.x = fmaxf(acc.x + bb.x, 0.0f);
    acc.y = fmaxf(acc.y + bb.y, 0.0f);
    acc.z = fmaxf(acc.z + bb.z, 0.0f);
    acc.w = fmaxf(acc.w + bb.w, 0.0f);
    reinterpret_cast<float4*>(g_h)[(size_t)node * 32 + lane] = acc;
}

// ---------------- layer-2 aggregation + bias + log_softmax ----------------
__global__ __launch_bounds__(256)
void k_agg2(const float* __restrict__ b2, float* __restrict__ out) {
    int node = (blockIdx.x * blockDim.x + threadIdx.x) >> 5;
    int lane = threadIdx.x & 31;
    if (node >= N_NODES) return;
    float di = g_dinv[node];
    float acc = di * di * g_hw2[(size_t)node * N_CLS + lane];
    int start = g_rowstart[node];
    int cnt = g_deg[node];
#pragma unroll 4
    for (int e = 0; e < cnt; e++) {
        int s = g_csr_src[start + e];
        float w = di * g_dinv[s];
        acc += w * g_hw2[(size_t)s * N_CLS + lane];
    }
    acc += b2[lane];
    // log_softmax over the 32 lanes
    float m = acc;
#pragma unroll
    for (int off = 16; off > 0; off >>= 1)
        m = fmaxf(m, __shfl_xor_sync(0xFFFFFFFFu, m, off));
    float ex = expf(acc - m);
    float sum = ex;
#pragma unroll
    for (int off = 16; off > 0; off >>= 1)
        sum += __shfl_xor_sync(0xFFFFFFFFu, sum, off);
    out[(size_t)node * N_CLS + lane] = acc - m - logf(sum);
}

// ---------------- launch ----------------
extern "C" void kernel_launch(void* const* d_in, const int* in_sizes, int n_in,
                              void* d_out, int out_size) {
    const float* features = nullptr;
    const void*  eidx = nullptr;
    const float* W1 = nullptr;
    const float* b1 = nullptr;
    const float* W2 = nullptr;
    const float* b2 = nullptr;
    for (int i = 0; i < n_in; i++) {
        switch (in_sizes[i]) {
            case N_NODES * F_IN: features = (const float*)d_in[i]; break;
            case 2 * N_EDGES:    eidx = d_in[i]; break;
            case F_IN * HID:     W1 = (const float*)d_in[i]; break;
            case HID:            b1 = (const float*)d_in[i]; break;
            case HID * N_CLS:    W2 = (const float*)d_in[i]; break;
            case N_CLS:          b2 = (const float*)d_in[i]; break;
            default: break;
        }
    }

    void *p_xw = nullptr, *p_h = nullptr, *p_hw2 = nullptr;
    cudaGetSymbolAddress(&p_xw, g_xw);
    cudaGetSymbolAddress(&p_h, g_h);
    cudaGetSymbolAddress(&p_hw2, g_hw2);

    // preprocessing
    k_detect<<<1, 32>>>((const int*)eidx);
    k_init<<<(N_NODES + 255) / 256, 256>>>();
    k_convert<<<(N_EDGES + 255) / 256, 256>>>(eidx);
    k_dinv<<<(N_NODES + 255) / 256, 256>>>();
    k_scan<<<1, 512>>>();
    k_fill<<<(N_EDGES + 255) / 256, 256>>>();

    // layer 1: XW1 (tf32 tensor cores) then aggregate+bias+relu
    {
        int grid = (N_NODES + 127) / 128;  // 782
        k_gemm1_tf32<<<grid, 256>>>(features, W1, (float*)p_xw);
    }
    k_agg1<<<(N_NODES * 32 + 255) / 256, 256>>>(b1);

    // layer 2: HW2 then aggregate+bias+log_softmax
    {
        constexpr int BM = 128;
        int grid = (N_NODES + BM - 1) / BM;
        k_sgemm<BM, 32, 16, 8, 4><<<grid, 128>>>((const float*)p_h, W2, (float*)p_hw2,
                                                 N_NODES, N_CLS, HID);
    }
    k_agg2<<<(N_NODES * 32 + 255) / 256, 256>>>(b2, (float*)d_out);
}